// round 3
// baseline (speedup 1.0000x reference)
#include <cuda_runtime.h>
#include <math.h>

// ---------------- problem constants ----------------
#define BB 8
#define SS 4096
#define EE 1024
#define SD 8
#define MM (BB*SS)          // 32768
#define LDIN 1032           // E + SD

// ---------------- scratch (device globals, no allocs) ----------------
__device__ float g_Weff[EE * EE];        // W_in[:, :E] @ W_out[:E, :]   (4 MB)
__device__ float g_Wg_eff[EE * SD];      // W_in @ W_g
__device__ float g_bg_eff[SD];
__device__ float g_bout_eff[EE];
__device__ float g_gate[MM * SD];
__device__ float g_si[MM * SD];
__device__ float g_states[MM * SD];

// ---------------- precompute small folded weights ----------------
__global__ void precompute_kernel(const float* __restrict__ W_in,
                                  const float* __restrict__ W_g,
                                  const float* __restrict__ b_g,
                                  const float* __restrict__ b_in,
                                  const float* __restrict__ W_out,
                                  const float* __restrict__ b_out,
                                  float* __restrict__ Wg_eff,
                                  float* __restrict__ bg_eff,
                                  float* __restrict__ bout_eff)
{
    int gid = blockIdx.x * blockDim.x + threadIdx.x;
    if (gid < EE * SD) {
        int e = gid >> 3, d = gid & 7;
        float s = 0.f;
        const float* wr = W_in + (size_t)e * LDIN;
        #pragma unroll 4
        for (int c = 0; c < LDIN; c++) s = fmaf(wr[c], W_g[c * SD + d], s);
        Wg_eff[e * SD + d] = s;
    } else if (gid < EE * SD + SD) {
        int d = gid - EE * SD;
        float s = b_g[d];
        for (int c = 0; c < LDIN; c++) s = fmaf(b_in[c], W_g[c * SD + d], s);
        bg_eff[d] = s;
    } else if (gid < EE * SD + SD + EE) {
        int n = gid - (EE * SD + SD);
        float s = b_out[n];
        for (int c = 0; c < EE; c++) s = fmaf(b_in[c], W_out[(size_t)c * EE + n], s);
        bout_eff[n] = s;
    }
}

// ---------------- tiled fp32 SGEMM: C = A(MxK, lda) * B(KxN, ldb) [+ epilogue] ----
// 128x128 block tile, BK=8, 256 threads, 8x8 per thread.
// Optional epilogue: C += Srank(Mx8) * Wbot(8xN, ld=ldc) + bias(N)
#define BM 128
#define BN 128
#define BK 8

__global__ __launch_bounds__(256, 2)
void sgemm_kernel(const float* __restrict__ A, int lda,
                  const float* __restrict__ B, int ldb,
                  float* __restrict__ C, int ldc,
                  int K,
                  const float* __restrict__ bias,     // or null
                  const float* __restrict__ Srank,    // [M,8] or null
                  const float* __restrict__ Wbot)     // [8, N] ld ldc, or null
{
    __shared__ float As[BK][BM];
    __shared__ float Bs[BK][BN];
    __shared__ float sWb[SD][BN];
    __shared__ float sSt[BM * SD];
    __shared__ float sBias[BN];

    const int tid = threadIdx.x;
    const int tx = tid & 15;          // 0..15 -> n
    const int ty = tid >> 4;          // 0..15 -> m
    const int bn0 = blockIdx.x * BN;
    const int bm0 = blockIdx.y * BM;

    // epilogue data loads (consumed only after many syncthreads)
    if (Wbot != nullptr) {
        // 8 x 128 W rows
        for (int idx = tid; idx < SD * BN; idx += 256) {
            int d = idx >> 7, nl = idx & 127;
            sWb[d][nl] = Wbot[(size_t)d * ldc + bn0 + nl];
        }
        // 128 rows x 8 states -> 1024 floats, float4 per thread
        *((float4*)&sSt[tid * 4]) = *((const float4*)&Srank[(size_t)bm0 * SD + tid * 4]);
        if (tid < BN) sBias[tid] = bias[bn0 + tid];
    }

    const int rowA  = tid >> 1;          // 0..127
    const int colA4 = (tid & 1) * 4;     // 0 or 4
    const int rowB  = tid >> 5;          // 0..7
    const int colB4 = (tid & 31) * 4;

    const float* Aptr = A + (size_t)(bm0 + rowA) * lda + colA4;
    const float* Bptr = B + (size_t)rowB * ldb + bn0 + colB4;

    float acc[8][8];
    #pragma unroll
    for (int i = 0; i < 8; i++)
        #pragma unroll
        for (int j = 0; j < 8; j++) acc[i][j] = 0.f;

    for (int k0 = 0; k0 < K; k0 += BK) {
        float4 a4 = *((const float4*)Aptr);
        float4 b4 = *((const float4*)Bptr);
        As[colA4 + 0][rowA] = a4.x;
        As[colA4 + 1][rowA] = a4.y;
        As[colA4 + 2][rowA] = a4.z;
        As[colA4 + 3][rowA] = a4.w;
        *((float4*)&Bs[rowB][colB4]) = b4;
        __syncthreads();

        #pragma unroll
        for (int k = 0; k < BK; k++) {
            float4 ra0 = *((const float4*)&As[k][ty * 8]);
            float4 ra1 = *((const float4*)&As[k][ty * 8 + 4]);
            float4 rb0 = *((const float4*)&Bs[k][tx * 8]);
            float4 rb1 = *((const float4*)&Bs[k][tx * 8 + 4]);
            float ra[8] = {ra0.x, ra0.y, ra0.z, ra0.w, ra1.x, ra1.y, ra1.z, ra1.w};
            float rb[8] = {rb0.x, rb0.y, rb0.z, rb0.w, rb1.x, rb1.y, rb1.z, rb1.w};
            #pragma unroll
            for (int i = 0; i < 8; i++)
                #pragma unroll
                for (int j = 0; j < 8; j++)
                    acc[i][j] = fmaf(ra[i], rb[j], acc[i][j]);
        }
        __syncthreads();
        Aptr += BK;
        Bptr += (size_t)BK * ldb;
    }

    // epilogue + store
    #pragma unroll
    for (int i = 0; i < 8; i++) {
        int ml = ty * 8 + i;
        size_t crow = (size_t)(bm0 + ml) * ldc + bn0;
        float v[8];
        #pragma unroll
        for (int j = 0; j < 8; j++) v[j] = acc[i][j];
        if (Wbot != nullptr) {
            #pragma unroll
            for (int j = 0; j < 8; j++) {
                int nl = tx * 8 + j;
                float s = v[j] + sBias[nl];
                #pragma unroll
                for (int d = 0; d < SD; d++)
                    s = fmaf(sSt[ml * SD + d], sWb[d][nl], s);
                v[j] = s;
            }
        }
        float4 o0 = {v[0], v[1], v[2], v[3]};
        float4 o1 = {v[4], v[5], v[6], v[7]};
        *((float4*)&C[crow + tx * 8])     = o0;
        *((float4*)&C[crow + tx * 8 + 4]) = o1;
    }
}

// ---------------- skinny pass: gate + state_in (N=16 over K=1024) ----------------
// warp per group of 4 rows; weights staged in smem transposed [16][512] per phase.
__global__ __launch_bounds__(256)
void gate_si_kernel(const float* __restrict__ x,
                    const float* __restrict__ Wg_eff,   // [E][8]
                    const float* __restrict__ W_in,     // for si columns
                    const float* __restrict__ bg_eff,   // [8]
                    const float* __restrict__ b_in,     // [1032]
                    float* __restrict__ gate,
                    float* __restrict__ si)
{
    __shared__ float sWT[16][512];
    const int tid = threadIdx.x;
    const int lane = tid & 31;
    const int warp = tid >> 5;           // 0..7
    const int m0 = blockIdx.x * 32 + warp * 4;

    float acc[4][16];
    #pragma unroll
    for (int r = 0; r < 4; r++)
        #pragma unroll
        for (int d = 0; d < 16; d++) acc[r][d] = 0.f;

    for (int p = 0; p < 2; p++) {
        for (int idx = tid; idx < 16 * 512; idx += 256) {
            int d = idx >> 9, el = idx & 511;
            int e = p * 512 + el;
            sWT[d][el] = (d < 8) ? Wg_eff[e * SD + d]
                                 : W_in[(size_t)e * LDIN + EE + (d - 8)];
        }
        __syncthreads();

        for (int eb = 0; eb < 512; eb += 32) {
            float xv[4];
            #pragma unroll
            for (int r = 0; r < 4; r++)
                xv[r] = x[(size_t)(m0 + r) * EE + p * 512 + eb + lane];
            #pragma unroll
            for (int d = 0; d < 16; d++) {
                float w = sWT[d][eb + lane];
                #pragma unroll
                for (int r = 0; r < 4; r++)
                    acc[r][d] = fmaf(xv[r], w, acc[r][d]);
            }
        }
        __syncthreads();
    }

    // reduce across 32 lanes (each lane held e = lane mod 32)
    #pragma unroll
    for (int r = 0; r < 4; r++) {
        #pragma unroll
        for (int d = 0; d < 16; d++) {
            float v = acc[r][d];
            v += __shfl_xor_sync(0xffffffffu, v, 16);
            v += __shfl_xor_sync(0xffffffffu, v, 8);
            v += __shfl_xor_sync(0xffffffffu, v, 4);
            v += __shfl_xor_sync(0xffffffffu, v, 2);
            v += __shfl_xor_sync(0xffffffffu, v, 1);
            acc[r][d] = v;
        }
        int m = m0 + r;
        if (lane < 8) {
            float logit = acc[r][lane] + bg_eff[lane];
            gate[m * SD + lane] = 1.0f / (1.0f + expf(-logit));
        } else if (lane < 16) {
            si[m * SD + (lane - 8)] = acc[r][lane] + b_in[EE + (lane - 8)];
        }
    }
}

// ---------------- sequential scan: 64 independent chains ----------------
__global__ void scan_kernel(const float* __restrict__ gate,
                            const float* __restrict__ si,
                            float* __restrict__ states,
                            float* __restrict__ final_state)
{
    int t = threadIdx.x;            // 0..63
    int b = t >> 3, d = t & 7;
    const float* gp = gate + (size_t)b * SS * SD + d;
    const float* sp = si   + (size_t)b * SS * SD + d;
    float*       op = states + (size_t)b * SS * SD + d;

    float st = 0.f;
    for (int s = 0; s < SS; s += 16) {
        float g[16], c[16];
        #pragma unroll
        for (int u = 0; u < 16; u++) {
            g[u] = gp[(s + u) * SD];
            float sv = sp[(s + u) * SD];
            c[u] = sv - g[u] * sv;      // (1-g)*si off the dependent chain
        }
        #pragma unroll
        for (int u = 0; u < 16; u++) {
            st = fmaf(g[u], st, c[u]);  // single FMA on the chain
            op[(s + u) * SD] = st;
        }
    }
    final_state[b * SD + d] = st;
}

// ---------------- launch ----------------
extern "C" void kernel_launch(void* const* d_in, const int* in_sizes, int n_in,
                              void* d_out, int out_size)
{
    const float* x     = (const float*)d_in[0];
    const float* W_in  = (const float*)d_in[1];
    const float* b_in  = (const float*)d_in[2];
    const float* W_g   = (const float*)d_in[3];
    const float* b_g   = (const float*)d_in[4];
    const float* W_out = (const float*)d_in[5];
    const float* b_out = (const float*)d_in[6];
    float* out = (float*)d_out;

    float *Weff, *Wg_eff, *bg_eff, *bout_eff, *gate, *si, *states;
    cudaGetSymbolAddress((void**)&Weff,     g_Weff);
    cudaGetSymbolAddress((void**)&Wg_eff,   g_Wg_eff);
    cudaGetSymbolAddress((void**)&bg_eff,   g_bg_eff);
    cudaGetSymbolAddress((void**)&bout_eff, g_bout_eff);
    cudaGetSymbolAddress((void**)&gate,     g_gate);
    cudaGetSymbolAddress((void**)&si,       g_si);
    cudaGetSymbolAddress((void**)&states,   g_states);

    // 1) small folded weights
    int tot = EE * SD + SD + EE;
    precompute_kernel<<<(tot + 255) / 256, 256>>>(W_in, W_g, b_g, b_in, W_out, b_out,
                                                  Wg_eff, bg_eff, bout_eff);

    // 2) W_eff = W_in[:, :E] @ W_out[:E, :]   (1024x1024x1024)
    sgemm_kernel<<<dim3(EE / BN, EE / BM), 256>>>(W_in, LDIN, W_out, EE,
                                                  Weff, EE, EE,
                                                  nullptr, nullptr, nullptr);

    // 3) gate + state_in directly from x (skinny N=16)
    gate_si_kernel<<<MM / 32, 256>>>(x, Wg_eff, W_in, bg_eff, b_in, gate, si);

    // 4) sequential scan (also writes final_state at tail of output)
    scan_kernel<<<1, 64>>>(gate, si, states, out + (size_t)MM * EE);

    // 5) out = x @ W_eff + states @ W_out[E:, :] + bout_eff
    sgemm_kernel<<<dim3(EE / BN, MM / BM), 256>>>(x, EE, Weff, EE,
                                                  out, EE, EE,
                                                  bout_eff, states,
                                                  W_out + (size_t)EE * EE);
}

// round 5
// speedup vs baseline: 2.8589x; 2.8589x over previous
#include <cuda_runtime.h>
#include <cuda_bf16.h>
#include <math.h>
#include <stdint.h>

// ---------------- problem constants ----------------
#define BB 8
#define SS 4096
#define EE 1024
#define SD 8
#define MM (BB*SS)          // 32768
#define LDIN 1032           // E + SD
#define GK 3072             // split-bf16 3-term K
#define NIT 48              // GK / 64

// ================= portable PTX helpers (sm_80+) =================
__device__ __forceinline__ uint32_t smem_to_u32(const void* smem_ptr) {
    uint32_t addr;
    asm("{ .reg .u64 tmp; cvta.to.shared.u64 tmp, %1; cvt.u32.u64 %0, tmp; }"
        : "=r"(addr) : "l"(smem_ptr));
    return addr;
}

#define CP_ASYNC16(dst, src) \
    asm volatile("cp.async.cg.shared.global [%0], [%1], 16;" \
                 :: "r"(dst), "l"(src) : "memory")
#define CP_COMMIT() asm volatile("cp.async.commit_group;" ::: "memory")
#define CP_WAIT1()  asm volatile("cp.async.wait_group 1;"  ::: "memory")

__device__ __forceinline__ void ldsm_x4(uint32_t& r0, uint32_t& r1,
                                        uint32_t& r2, uint32_t& r3,
                                        uint32_t addr) {
    asm volatile("ldmatrix.sync.aligned.m8n8.x4.shared.b16 {%0,%1,%2,%3}, [%4];"
                 : "=r"(r0), "=r"(r1), "=r"(r2), "=r"(r3) : "r"(addr));
}

__device__ __forceinline__ void mma16816(float* d, const uint32_t* a,
                                         const uint32_t* b) {
    asm volatile("mma.sync.aligned.m16n8k16.row.col.f32.bf16.bf16.f32 "
                 "{%0,%1,%2,%3}, {%4,%5,%6,%7}, {%8,%9}, {%0,%1,%2,%3};"
                 : "+f"(d[0]), "+f"(d[1]), "+f"(d[2]), "+f"(d[3])
                 : "r"(a[0]), "r"(a[1]), "r"(a[2]), "r"(a[3]),
                   "r"(b[0]), "r"(b[1]));
}

// ---------------- scratch (device globals, no allocs) ----------------
__device__ float g_Weff[EE * EE];
__device__ float g_Wg_eff[EE * SD];
__device__ float g_bg_eff[SD];
__device__ float g_bout_eff[EE];
__device__ float g_gate[MM * SD];
__device__ float g_si[MM * SD];
__device__ float g_states[MM * SD];
__device__ __nv_bfloat16 g_Ax[(size_t)MM * GK];
__device__ __nv_bfloat16 g_Awin[(size_t)EE * GK];
__device__ __nv_bfloat16 g_Bwout[(size_t)EE * GK];
__device__ __nv_bfloat16 g_Bweff[(size_t)EE * GK];

// ---------------- precompute small folded weights ----------------
__global__ void precompute_kernel(const float* __restrict__ W_in,
                                  const float* __restrict__ W_g,
                                  const float* __restrict__ b_g,
                                  const float* __restrict__ b_in,
                                  const float* __restrict__ W_out,
                                  const float* __restrict__ b_out,
                                  float* __restrict__ Wg_eff,
                                  float* __restrict__ bg_eff,
                                  float* __restrict__ bout_eff)
{
    int gid = blockIdx.x * blockDim.x + threadIdx.x;
    if (gid < EE * SD) {
        int e = gid >> 3, d = gid & 7;
        float s = 0.f;
        const float* wr = W_in + (size_t)e * LDIN;
        #pragma unroll 4
        for (int c = 0; c < LDIN; c++) s = fmaf(wr[c], W_g[c * SD + d], s);
        Wg_eff[e * SD + d] = s;
    } else if (gid < EE * SD + SD) {
        int d = gid - EE * SD;
        float s = b_g[d];
        for (int c = 0; c < LDIN; c++) s = fmaf(b_in[c], W_g[c * SD + d], s);
        bg_eff[d] = s;
    } else if (gid < EE * SD + SD + EE) {
        int n = gid - (EE * SD + SD);
        float s = b_out[n];
        for (int c = 0; c < EE; c++) s = fmaf(b_in[c], W_out[(size_t)c * EE + n], s);
        bout_eff[n] = s;
    }
}

// ---------------- hi/lo bf16 decomposition, row-major source ----------------
// dst[r] = [hi(0:1024) | hi(1024:2048) | lo(2048:3072)]
__global__ void decompose_rows_kernel(const float* __restrict__ src, int srcld,
                                      __nv_bfloat16* __restrict__ dst)
{
    int r = blockIdx.x;
    int c4 = threadIdx.x * 4;
    float4 v = *(const float4*)(src + (size_t)r * srcld + c4);
    struct alignas(8) B4 { __nv_bfloat16 b[4]; };
    B4 H, L;
    float vv[4] = {v.x, v.y, v.z, v.w};
    #pragma unroll
    for (int i = 0; i < 4; i++) {
        __nv_bfloat16 h = __float2bfloat16(vv[i]);
        H.b[i] = h;
        L.b[i] = __float2bfloat16(vv[i] - __bfloat162float(h));
    }
    __nv_bfloat16* row = dst + (size_t)r * GK;
    *(B4*)(row + c4)        = H;
    *(B4*)(row + 1024 + c4) = H;
    *(B4*)(row + 2048 + c4) = L;
}

// ---------------- hi/lo bf16 decomposition, transposed source -------------
// src [1024][1024] fp32; dst[n] = [hi(col n) | lo(col n) | hi(col n)]
__global__ void decompose_trans_kernel(const float* __restrict__ src,
                                       __nv_bfloat16* __restrict__ dst)
{
    __shared__ float tile[32][33];
    int e0 = blockIdx.x * 32, n0 = blockIdx.y * 32;
    int tx = threadIdx.x, ty = threadIdx.y;     // 32 x 8
    #pragma unroll
    for (int i = 0; i < 4; i++)
        tile[ty + i * 8][tx] = src[(size_t)(e0 + ty + i * 8) * 1024 + n0 + tx];
    __syncthreads();
    #pragma unroll
    for (int i = 0; i < 4; i++) {
        int n = n0 + ty + i * 8;
        float v = tile[tx][ty + i * 8];
        __nv_bfloat16 h = __float2bfloat16(v);
        __nv_bfloat16 l = __float2bfloat16(v - __bfloat162float(h));
        __nv_bfloat16* row = dst + (size_t)n * GK;
        row[e0 + tx]        = h;
        row[1024 + e0 + tx] = l;
        row[2048 + e0 + tx] = h;
    }
}

// ================= warp-mma bf16 GEMM (family-target safe) =================
// C[m][n] = sum_k A[m][k]*B[n][k]; A:[M,3072] bf16, B:[1024,3072] bf16 (n rows),
// C fp32 ld 1024. CTA 128x128, BK=64, 8 warps (64x32 each), cp.async dbl-buf.
// Optional epilogue: C += bias[n] + Srank[m][.]·Wbot[.][n]  (Wbot ld 1024).
__global__ void __launch_bounds__(256, 2)
gemm_mma_kernel(const __nv_bfloat16* __restrict__ A,
                const __nv_bfloat16* __restrict__ Bm,
                float* __restrict__ C,
                const float* __restrict__ bias,
                const float* __restrict__ Srank,
                const float* __restrict__ Wbot)
{
    extern __shared__ char smem[];               // 64 KB: A0 A1 B0 B1 (16KB each)
    const uint32_t sb = smem_to_u32(smem);
    const int tid  = threadIdx.x;
    const int lane = tid & 31;
    const int wid  = tid >> 5;
    const int wm   = wid >> 2;                   // 0..1
    const int wn   = wid & 3;                    // 0..3
    const int n0   = blockIdx.x * 128;
    const int m0   = blockIdx.y * 128;

    float acc[4][4][4];
    #pragma unroll
    for (int mi = 0; mi < 4; mi++)
        #pragma unroll
        for (int ni = 0; ni < 4; ni++)
            #pragma unroll
            for (int e = 0; e < 4; e++) acc[mi][ni][e] = 0.f;

    // per-thread gmem->smem chunks: 1024 chunks of 16B per (A or B) tile
    // chunk c: row = c>>3, seg = c&7; swizzled 128B rows
    auto prefetch = [&](int buf, int kb) {
        const uint32_t aOff = buf * 16384u;
        const uint32_t bOff = 32768u + buf * 16384u;
        #pragma unroll
        for (int i = 0; i < 4; i++) {
            int c   = tid + i * 256;
            int row = c >> 3, seg = c & 7;
            uint32_t sw = (uint32_t)row * 128u + (uint32_t)((seg ^ (row & 7)) * 16);
            CP_ASYNC16(sb + aOff + sw, A  + (size_t)(m0 + row) * GK + kb + seg * 8);
            CP_ASYNC16(sb + bOff + sw, Bm + (size_t)(n0 + row) * GK + kb + seg * 8);
        }
    };

    prefetch(0, 0);
    CP_COMMIT();

    // ldmatrix per-thread row offsets
    const int rA   = ((lane >> 3) & 1) * 8 + (lane & 7);   // row within m16
    const int kA8  = lane >> 4;                            // k 8-block select
    const int rB   = (lane >> 4) * 8 + (lane & 7);         // row within n16
    const int kB8  = (lane >> 3) & 1;

    for (int it = 0; it < NIT; it++) {
        const int buf = it & 1;
        if (it + 1 < NIT) prefetch((it + 1) & 1, (it + 1) * 64);
        CP_COMMIT();
        CP_WAIT1();
        __syncthreads();

        const uint32_t aB = sb + buf * 16384u;
        const uint32_t bB = sb + 32768u + buf * 16384u;

        #pragma unroll
        for (int ks = 0; ks < 4; ks++) {
            uint32_t af[4][4], bf[4][2];
            #pragma unroll
            for (int mi = 0; mi < 4; mi++) {
                int row = wm * 64 + mi * 16 + rA;
                int seg = ks * 2 + kA8;
                ldsm_x4(af[mi][0], af[mi][1], af[mi][2], af[mi][3],
                        aB + (uint32_t)row * 128u + (uint32_t)((seg ^ (row & 7)) * 16));
            }
            #pragma unroll
            for (int np = 0; np < 2; np++) {
                int row = wn * 32 + np * 16 + rB;
                int seg = ks * 2 + kB8;
                uint32_t r0, r1, r2, r3;
                ldsm_x4(r0, r1, r2, r3,
                        bB + (uint32_t)row * 128u + (uint32_t)((seg ^ (row & 7)) * 16));
                bf[np * 2][0] = r0;     bf[np * 2][1] = r1;
                bf[np * 2 + 1][0] = r2; bf[np * 2 + 1][1] = r3;
            }
            #pragma unroll
            for (int mi = 0; mi < 4; mi++)
                #pragma unroll
                for (int ni = 0; ni < 4; ni++)
                    mma16816(acc[mi][ni], af[mi], bf[ni]);
        }
        __syncthreads();
    }

    // ---------------- epilogue ----------------
    const bool epi = (Srank != nullptr);
    float* const sBias = (float*)smem;                 // 128 f
    float* const sSt   = (float*)(smem + 512);         // 128 x 8
    float* const sWb   = (float*)(smem + 512 + 4096);  // 8 x 128
    if (epi) {
        if (tid < 128) sBias[tid] = bias[n0 + tid];
        ((float4*)sSt)[tid] = ((const float4*)(Srank + (size_t)m0 * SD))[tid];
        for (int i = tid; i < 1024; i += 256) {
            int d8 = i >> 7, nl = i & 127;
            sWb[d8 * 128 + nl] = Wbot[(size_t)d8 * 1024 + n0 + nl];
        }
    }
    __syncthreads();

    const int lr  = lane >> 2;
    const int lc2 = (lane & 3) * 2;
    #pragma unroll
    for (int mi = 0; mi < 4; mi++) {
        int r0l = wm * 64 + mi * 16 + lr;
        int r1l = r0l + 8;
        float st0[SD], st1[SD];
        if (epi) {
            #pragma unroll
            for (int d = 0; d < SD; d++) {
                st0[d] = sSt[r0l * SD + d];
                st1[d] = sSt[r1l * SD + d];
            }
        }
        #pragma unroll
        for (int ni = 0; ni < 4; ni++) {
            int cg = wn * 32 + ni * 8 + lc2;
            float* d = acc[mi][ni];
            if (epi) {
                float s00 = sBias[cg], s01 = sBias[cg + 1];
                float s10 = s00, s11 = s01;
                #pragma unroll
                for (int dd = 0; dd < SD; dd++) {
                    float w0 = sWb[dd * 128 + cg], w1 = sWb[dd * 128 + cg + 1];
                    s00 = fmaf(st0[dd], w0, s00); s01 = fmaf(st0[dd], w1, s01);
                    s10 = fmaf(st1[dd], w0, s10); s11 = fmaf(st1[dd], w1, s11);
                }
                d[0] += s00; d[1] += s01; d[2] += s10; d[3] += s11;
            }
            float2 o0 = { d[0], d[1] };
            float2 o1 = { d[2], d[3] };
            *(float2*)(C + (size_t)(m0 + r0l) * 1024 + n0 + cg) = o0;
            *(float2*)(C + (size_t)(m0 + r1l) * 1024 + n0 + cg) = o1;
        }
    }
}

// ---------------- skinny pass: gate + state_in ----------------
__global__ __launch_bounds__(256)
void gate_si_kernel(const float* __restrict__ x,
                    const float* __restrict__ Wg_eff,
                    const float* __restrict__ W_in,
                    const float* __restrict__ bg_eff,
                    const float* __restrict__ b_in,
                    float* __restrict__ gate,
                    float* __restrict__ si)
{
    __shared__ float sWT[16][512];
    const int tid = threadIdx.x;
    const int lane = tid & 31;
    const int warp = tid >> 5;
    const int m0 = blockIdx.x * 32 + warp * 4;

    float acc[4][16];
    #pragma unroll
    for (int r = 0; r < 4; r++)
        #pragma unroll
        for (int d = 0; d < 16; d++) acc[r][d] = 0.f;

    for (int p = 0; p < 2; p++) {
        for (int idx = tid; idx < 16 * 512; idx += 256) {
            int d = idx >> 9, el = idx & 511;
            int e = p * 512 + el;
            sWT[d][el] = (d < 8) ? Wg_eff[e * SD + d]
                                 : W_in[(size_t)e * LDIN + EE + (d - 8)];
        }
        __syncthreads();

        for (int eb = 0; eb < 512; eb += 32) {
            float xv[4];
            #pragma unroll
            for (int r = 0; r < 4; r++)
                xv[r] = x[(size_t)(m0 + r) * EE + p * 512 + eb + lane];
            #pragma unroll
            for (int d = 0; d < 16; d++) {
                float w = sWT[d][eb + lane];
                #pragma unroll
                for (int r = 0; r < 4; r++)
                    acc[r][d] = fmaf(xv[r], w, acc[r][d]);
            }
        }
        __syncthreads();
    }

    #pragma unroll
    for (int r = 0; r < 4; r++) {
        #pragma unroll
        for (int d = 0; d < 16; d++) {
            float v = acc[r][d];
            v += __shfl_xor_sync(0xffffffffu, v, 16);
            v += __shfl_xor_sync(0xffffffffu, v, 8);
            v += __shfl_xor_sync(0xffffffffu, v, 4);
            v += __shfl_xor_sync(0xffffffffu, v, 2);
            v += __shfl_xor_sync(0xffffffffu, v, 1);
            acc[r][d] = v;
        }
        int m = m0 + r;
        if (lane < 8) {
            float logit = acc[r][lane] + bg_eff[lane];
            gate[m * SD + lane] = 1.0f / (1.0f + expf(-logit));
        } else if (lane < 16) {
            si[m * SD + (lane - 8)] = acc[r][lane] + b_in[EE + (lane - 8)];
        }
    }
}

// ---------------- parallel linear-recurrence scan ----------------
__global__ __launch_bounds__(128)
void scan_par_kernel(const float* __restrict__ gate,
                     const float* __restrict__ si,
                     float* __restrict__ states,
                     float* __restrict__ final_state)
{
    const int chain = blockIdx.x;            // 0..63
    const int b = chain >> 3, d = chain & 7;
    const int t = threadIdx.x;               // 0..127
    const int lane = t & 31, warp = t >> 5;
    const float* gp = gate + (size_t)b * SS * SD + d;
    const float* sp = si   + (size_t)b * SS * SD + d;
    float*       op = states + (size_t)b * SS * SD + d;
    const int s0 = t * 32;

    float g[32], cc[32];
    float G = 1.f, C = 0.f;
    #pragma unroll
    for (int u = 0; u < 32; u++) {
        float gv = gp[(s0 + u) * SD];
        float sv = sp[(s0 + u) * SD];
        float cv = sv - gv * sv;
        g[u] = gv; cc[u] = cv;
        C = fmaf(gv, C, cv);
        G = gv * G;
    }
    #pragma unroll
    for (int off = 1; off < 32; off <<= 1) {
        float pG = __shfl_up_sync(0xffffffffu, G, off);
        float pC = __shfl_up_sync(0xffffffffu, C, off);
        if (lane >= off) { C = fmaf(G, pC, C); G *= pG; }
    }
    __shared__ float wG[4], wC[4];
    if (lane == 31) { wG[warp] = G; wC[warp] = C; }
    __syncthreads();
    float preC = 0.f;
    for (int w = 0; w < warp; w++) { preC = fmaf(wG[w], preC, wC[w]); }
    float eG = __shfl_up_sync(0xffffffffu, G, 1);
    float eC = __shfl_up_sync(0xffffffffu, C, 1);
    if (lane == 0) { eG = 1.f; eC = 0.f; }
    float s = fmaf(eG, preC, eC);
    #pragma unroll
    for (int u = 0; u < 32; u++) {
        s = fmaf(g[u], s, cc[u]);
        op[(s0 + u) * SD] = s;
    }
    if (t == 127) final_state[b * SD + d] = s;
}

// ---------------- launch ----------------
extern "C" void kernel_launch(void* const* d_in, const int* in_sizes, int n_in,
                              void* d_out, int out_size)
{
    const float* x     = (const float*)d_in[0];
    const float* W_in  = (const float*)d_in[1];
    const float* b_in  = (const float*)d_in[2];
    const float* W_g   = (const float*)d_in[3];
    const float* b_g   = (const float*)d_in[4];
    const float* W_out = (const float*)d_in[5];
    const float* b_out = (const float*)d_in[6];
    float* out = (float*)d_out;

    float *Weff, *Wg_eff, *bg_eff, *bout_eff, *gate, *si, *states;
    __nv_bfloat16 *Ax, *Awin, *Bwout, *Bweff;
    cudaGetSymbolAddress((void**)&Weff,     g_Weff);
    cudaGetSymbolAddress((void**)&Wg_eff,   g_Wg_eff);
    cudaGetSymbolAddress((void**)&bg_eff,   g_bg_eff);
    cudaGetSymbolAddress((void**)&bout_eff, g_bout_eff);
    cudaGetSymbolAddress((void**)&gate,     g_gate);
    cudaGetSymbolAddress((void**)&si,       g_si);
    cudaGetSymbolAddress((void**)&states,   g_states);
    cudaGetSymbolAddress((void**)&Ax,       g_Ax);
    cudaGetSymbolAddress((void**)&Awin,     g_Awin);
    cudaGetSymbolAddress((void**)&Bwout,    g_Bwout);
    cudaGetSymbolAddress((void**)&Bweff,    g_Bweff);

    cudaFuncSetAttribute(gemm_mma_kernel,
                         cudaFuncAttributeMaxDynamicSharedMemorySize, 65536);

    // 1) small folded weights
    int tot = EE * SD + SD + EE;
    precompute_kernel<<<(tot + 255) / 256, 256>>>(W_in, W_g, b_g, b_in, W_out, b_out,
                                                  Wg_eff, bg_eff, bout_eff);

    // 2) decompose W_in top-square (rows) + W_out top-square (transposed)
    decompose_rows_kernel<<<EE, 256>>>(W_in, LDIN, Awin);
    decompose_trans_kernel<<<dim3(32, 32), dim3(32, 8)>>>(W_out, Bwout);

    // 3) Weff = W_in[:, :E] @ W_out[:E, :]  via split-bf16 mma GEMM
    gemm_mma_kernel<<<dim3(EE / 128, EE / 128), 256, 65536>>>(
        Awin, Bwout, Weff, nullptr, nullptr, nullptr);

    // 4) decompose Weff (transposed) + x (rows)
    decompose_trans_kernel<<<dim3(32, 32), dim3(32, 8)>>>(Weff, Bweff);
    decompose_rows_kernel<<<MM, 256>>>(x, EE, Ax);

    // 5) gate + state_in
    gate_si_kernel<<<MM / 32, 256>>>(x, Wg_eff, W_in, bg_eff, b_in, gate, si);

    // 6) parallel scan (also writes final_state at tail of output)
    scan_par_kernel<<<64, 128>>>(gate, si, states, out + (size_t)MM * EE);

    // 7) out = x @ Weff + states @ W_out[E:, :] + bout_eff
    gemm_mma_kernel<<<dim3(EE / 128, MM / 128), 256, 65536>>>(
        Ax, Bweff, out, bout_eff, states, W_out + (size_t)EE * EE);
}